// round 11
// baseline (speedup 1.0000x reference)
#include <cuda_runtime.h>
#include <math.h>

// Problem constants (from reference)
#define NPROJS 128
#define L_DIM  1024
#define S_DIM  256
#define SPACING 4.7952
#define MU0     0.013

#define NBLOCKS 64             // 8 warps/block, each warp handles 2 rows
#define NWARPS_TOTAL (NBLOCKS * 8)   // 512 arrivals at the accumulator

// Packed accumulator: bits [0:52)  fixed-point sum (scale 2^40; total < 2^45)
//                     bits [52:64) arrival count (512 < 2^12).
__device__ unsigned long long g_acc = 0ULL;

#define FIX_SCALE   1099511627776.0f      /* 2^40 */
#define FIX_INV     (1.0 / 1099511627776.0)
#define COUNT_ONE   (1ULL << 52)
#define SUM_MASK    ((1ULL << 52) - 1ULL)

__global__ void __launch_bounds__(256) edcc_fused_kernel(
    const float* __restrict__ projs, float base, float step,
    float* __restrict__ out)
{
    const unsigned int lane = threadIdx.x & 31u;
    const unsigned int warp = threadIdx.x >> 5;          // 0..7
    const unsigned int l0 = (blockIdx.x * 8u + warp) * 2u;  // first of 2 rows
    const unsigned int row_f4 = l0 * (S_DIM / 4);

    // Two used projection slices (i=127, j=29); one warp handles rows l0, l0+1.
    const float4* __restrict__ p4 = (const float4*)projs;
    const unsigned int ibase = 127u * (L_DIM * S_DIM / 4) + row_f4 + lane;
    const unsigned int jbase = 29u  * (L_DIM * S_DIM / 4) + row_f4 + lane;

    // Front-batch ALL 8 independent 16B loads (MLP=8: DRAM latency /8, PTW hidden)
    const float4 a0 = p4[ibase];            // row l0,   i-slice, first half
    const float4 a1 = p4[ibase + 32];       // row l0,   i-slice, second half
    const float4 a2 = p4[ibase + 64];       // row l0+1, i-slice, first half
    const float4 a3 = p4[ibase + 96];       // row l0+1, i-slice, second half
    const float4 b0 = p4[jbase];
    const float4 b1 = p4[jbase + 32];
    const float4 b2 = p4[jbase + 64];
    const float4 b3 = p4[jbase + 96];

    // Weights depend only on element index -> computed ONCE, reused for both
    // rows. MUFU work overlaps the in-flight loads.
    const float e0 = (float)(lane * 4u);
    const float e1 = (float)((lane + 32u) * 4u);
    const float w0 = __expf(fmaf(e0,        step, base));
    const float w1 = __expf(fmaf(e0 + 1.0f, step, base));
    const float w2 = __expf(fmaf(e0 + 2.0f, step, base));
    const float w3 = __expf(fmaf(e0 + 3.0f, step, base));
    const float u0 = __expf(fmaf(e1,        step, base));
    const float u1 = __expf(fmaf(e1 + 1.0f, step, base));
    const float u2 = __expf(fmaf(e1 + 2.0f, step, base));
    const float u3 = __expf(fmaf(e1 + 3.0f, step, base));

    // Row l0
    float vi0 = a0.x * w0 + a0.y * w1 + a0.z * w2 + a0.w * w3
              + a1.x * u0 + a1.y * u1 + a1.z * u2 + a1.w * u3;
    float vj0 = b0.x * w0 + b0.y * w1 + b0.z * w2 + b0.w * w3
              + b1.x * u0 + b1.y * u1 + b1.z * u2 + b1.w * u3;
    // Row l0+1
    float vi1 = a2.x * w0 + a2.y * w1 + a2.z * w2 + a2.w * w3
              + a3.x * u0 + a3.y * u1 + a3.z * u2 + a3.w * u3;
    float vj1 = b2.x * w0 + b2.y * w1 + b2.z * w2 + b2.w * w3
              + b3.x * u0 + b3.y * u1 + b3.z * u2 + b3.w * u3;

    // Four independent shuffle ladders pipeline (26-cyc SHFL latency hidden)
    #pragma unroll
    for (int off = 16; off > 0; off >>= 1) {
        vi0 += __shfl_down_sync(0xFFFFFFFFu, vi0, off);
        vj0 += __shfl_down_sync(0xFFFFFFFFu, vj0, off);
        vi1 += __shfl_down_sync(0xFFFFFFFFu, vi1, off);
        vj1 += __shfl_down_sync(0xFFFFFFFFu, vj1, off);
    }

    // Lane 0: two row terms -> one packed atomic. No barrier, no smem.
    // Integer adds commute -> bitwise deterministic across replays.
    if (lane == 0) {
        // den > 0 always: inputs uniform[0,1), weights > 0.
        const float t0 = (2.0f / (float)NPROJS) * fabsf(vi0 - vj0) / (vi0 + vj0);
        const float t1 = (2.0f / (float)NPROJS) * fabsf(vi1 - vj1) / (vi1 + vj1);
        const unsigned long long contrib =
            (unsigned long long)((t0 + t1) * FIX_SCALE) | COUNT_ONE;
        const unsigned long long old = atomicAdd(&g_acc, contrib);

        if ((old >> 52) == (unsigned long long)(NWARPS_TOTAL - 1)) {
            const unsigned long long total = (old + contrib) & SUM_MASK;
            out[0] = (float)((double)total * FIX_INV);  // mean over B=1
            g_acc = 0ULL;   // re-arm for next graph replay
        }
    }
}

extern "C" void kernel_launch(void* const* d_in, const int* in_sizes, int n_in,
                              void* d_out, int out_size)
{
    const float* projs = (const float*)d_in[0];
    float* out = (float*)d_out;

    // sigma = MU0 * tan((theta[127] - theta[29]) / 2), theta_k = 2*pi*k/128
    // Weight argument: arg(e) = sigma*SPACING*(s_start + e*SPACING)
    const double two_pi = 6.283185307179586;
    const double th_i = two_pi * 127.0 / 128.0;
    const double th_j = two_pi * 29.0 / 128.0;
    const double sigma = MU0 * tan((th_i - th_j) * 0.5);
    const double s_start = (-(double)S_DIM * SPACING + SPACING) * 0.5;
    const float base = (float)(sigma * SPACING * s_start);
    const float step = (float)(sigma * SPACING * SPACING);

    edcc_fused_kernel<<<NBLOCKS, 256>>>(projs, base, step, out);
}